// round 5
// baseline (speedup 1.0000x reference)
#include <cuda_runtime.h>
#include <cuda_bf16.h>
#include <math.h>
#include <stdint.h>

// Problem constants
#define BB 2
#define SS 2048
#define HH 2048
#define NHH 16
#define HDD 128
#define MROWS (BB * SS)   // 4096

// ---------------- scratch (no allocations allowed) ----------------
__device__ __nv_bfloat16 g_Qhi[(size_t)MROWS * HH];
__device__ __nv_bfloat16 g_Qlo[(size_t)MROWS * HH];
__device__ __nv_bfloat16 g_Khi[(size_t)MROWS * HH];
__device__ __nv_bfloat16 g_Klo[(size_t)MROWS * HH];
__device__ __nv_bfloat16 g_Vhi[(size_t)MROWS * HH];
__device__ __nv_bfloat16 g_Vlo[(size_t)MROWS * HH];
__device__ __nv_bfloat16 g_xhi[(size_t)MROWS * HH];
__device__ __nv_bfloat16 g_xlo[(size_t)MROWS * HH];
__device__ __nv_bfloat16 g_wthi[(size_t)HH * HH];
__device__ __nv_bfloat16 g_wtlo[(size_t)HH * HH];

// ================= PTX helpers (baseline sm_90-level ISA only) ===========
__device__ __forceinline__ uint32_t smem_u32(const void* p) {
    uint32_t a;
    asm("{ .reg .u64 t; cvta.to.shared.u64 t, %1; cvt.u32.u64 %0, t; }"
        : "=r"(a) : "l"(p));
    return a;
}

// 1D bulk async copy global->shared, completion via mbarrier tx-bytes
__device__ __forceinline__ void bulk_g2s(uint32_t dst, const void* src,
                                         uint32_t bytes, uint32_t mbar) {
    asm volatile(
        "cp.async.bulk.shared::cluster.global.mbarrier::complete_tx::bytes "
        "[%0], [%1], %2, [%3];"
        :: "r"(dst), "l"(src), "r"(bytes), "r"(mbar) : "memory");
}

#define MBARRIER_INIT(addr, cnt) \
    asm volatile("mbarrier.init.shared.b64 [%0], %1;" :: "r"(addr), "r"(cnt) : "memory")

#define MBARRIER_ARRIVE_EXPECT_TX(addr, bytes) \
    asm volatile("mbarrier.arrive.expect_tx.shared.b64 _, [%0], %1;" \
                 :: "r"(addr), "r"((uint32_t)(bytes)) : "memory")

#define MBARRIER_WAIT_PARITY(mbar_smem_addr, phase_parity) do { \
    uint32_t _mbar = (uint32_t)(mbar_smem_addr); \
    uint32_t _parity = (uint32_t)(phase_parity); \
    uint32_t _done; \
    asm volatile( \
        "{\n\t.reg .pred p;\n\t" \
        "mbarrier.try_wait.parity.acquire.cta.shared::cta.b64 p, [%1], %2;\n\t" \
        "selp.b32 %0, 1, 0, p;\n\t}" \
        : "=r"(_done) : "r"(_mbar), "r"(_parity) : "memory"); \
    if (!_done) { \
        asm volatile( \
            "{\n\t.reg .pred P1;\n\t" \
            "WAIT_LOOP_%=:\n\t" \
            "mbarrier.try_wait.parity.acquire.cta.shared::cta.b64 P1, [%0], %1, 0x989680;\n\t" \
            "@P1 bra.uni WAIT_DONE_%=;\n\t" \
            "bra.uni WAIT_LOOP_%=;\n\t" \
            "WAIT_DONE_%=:\n\t}" \
            :: "r"(_mbar), "r"(_parity) : "memory"); \
    } \
} while (0)

__device__ __forceinline__ void ldmat_x4(uint32_t* r, uint32_t addr) {
    asm volatile("ldmatrix.sync.aligned.m8n8.x4.shared.b16 {%0,%1,%2,%3}, [%4];"
                 : "=r"(r[0]), "=r"(r[1]), "=r"(r[2]), "=r"(r[3]) : "r"(addr));
}
__device__ __forceinline__ void ldmat_x4_t(uint32_t* r, uint32_t addr) {
    asm volatile("ldmatrix.sync.aligned.m8n8.x4.trans.shared.b16 {%0,%1,%2,%3}, [%4];"
                 : "=r"(r[0]), "=r"(r[1]), "=r"(r[2]), "=r"(r[3]) : "r"(addr));
}

__device__ __forceinline__ void mma_bf16(float* d, const uint32_t* a, const uint32_t* b) {
    asm volatile(
        "mma.sync.aligned.m16n8k16.row.col.f32.bf16.bf16.f32 "
        "{%0,%1,%2,%3}, {%4,%5,%6,%7}, {%8,%9}, {%0,%1,%2,%3};"
        : "+f"(d[0]), "+f"(d[1]), "+f"(d[2]), "+f"(d[3])
        : "r"(a[0]), "r"(a[1]), "r"(a[2]), "r"(a[3]), "r"(b[0]), "r"(b[1]));
}

__device__ __forceinline__ void split2(float a, float b, uint32_t& hi, uint32_t& lo) {
    __nv_bfloat16 ha = __float2bfloat16_rn(a);
    __nv_bfloat16 hb = __float2bfloat16_rn(b);
    __nv_bfloat162 h2 = __halves2bfloat162(ha, hb);
    hi = *(uint32_t*)&h2;
    __nv_bfloat162 l2 = __floats2bfloat162_rn(a - __bfloat162float(ha),
                                              b - __bfloat162float(hb));
    lo = *(uint32_t*)&l2;
}

// ================= bf16-split GEMM (mma.sync + bulk-copy loader) ==========
// C[M,N] = A[M,K] @ Bt[N,K]^T + bias.  128x128x64 tile, 2 mbarrier stages.
#define G_BM 128
#define G_BN 128
#define G_BK 64
#define G_STRIDE 72                           // bf16 elems per row (64+8 pad)
#define G_ARR_BYTES (128 * G_STRIDE * 2)      // 18432
#define G_STAGE_BYTES (4 * G_ARR_BYTES)       // 73728
#define G_SMEM_BYTES (2 * G_STAGE_BYTES)      // 147456
#define G_STAGE_TX (512 * 128)                // 64 KB per stage

__global__ __launch_bounds__(256, 1)
void gemm_tc_kernel(const __nv_bfloat16* __restrict__ Ahi,
                    const __nv_bfloat16* __restrict__ Alo,
                    const __nv_bfloat16* __restrict__ Bhi,
                    const __nv_bfloat16* __restrict__ Blo,
                    const float* __restrict__ bias,
                    float* __restrict__ Cf,
                    __nv_bfloat16* __restrict__ Chi,
                    __nv_bfloat16* __restrict__ Clo,
                    int Kd, int Nd)
{
    extern __shared__ __align__(128) unsigned char dynsm[];
    __shared__ __align__(16) uint64_t s_mb[2];

    const int tid = threadIdx.x;
    const int wid = tid >> 5;
    const int lane = tid & 31;
    const int wm = wid & 1;
    const int wn = wid >> 1;
    const int bm = blockIdx.y * G_BM;
    const int bn = blockIdx.x * G_BN;
    const int NK = Kd / G_BK;   // 32

    const uint32_t smem_base = smem_u32(dynsm);
    uint32_t mb[2];
    mb[0] = smem_u32(&s_mb[0]);
    mb[1] = smem_u32(&s_mb[1]);

    if (tid == 0) {
        MBARRIER_INIT(mb[0], 1);
        MBARRIER_INIT(mb[1], 1);
    }
    __syncthreads();

    // issue one stage: 512 rows x 128B, 2 rows per thread
    auto issue_stage = [&](int st, int kt) {
        if (tid == 0) MBARRIER_ARRIVE_EXPECT_TX(mb[st], G_STAGE_TX);
        const int k0 = kt * G_BK;
        const uint32_t sb = smem_base + st * G_STAGE_BYTES;
#pragma unroll
        for (int v = 0; v < 2; v++) {
            const int idx = tid * 2 + v;       // 0..511
            const int arr = idx >> 7;
            const int r = idx & 127;
            const uint32_t dst = sb + arr * G_ARR_BYTES + r * (G_STRIDE * 2);
            const __nv_bfloat16* g;
            if (arr == 0)      g = Ahi + (size_t)(bm + r) * Kd + k0;
            else if (arr == 1) g = Alo + (size_t)(bm + r) * Kd + k0;
            else if (arr == 2) g = Bhi + (size_t)(bn + r) * Kd + k0;
            else               g = Blo + (size_t)(bn + r) * Kd + k0;
            bulk_g2s(dst, g, 128, mb[st]);
        }
    };

    float acc[4][4][4];
#pragma unroll
    for (int i = 0; i < 4; i++)
#pragma unroll
        for (int j = 0; j < 4; j++)
#pragma unroll
            for (int c = 0; c < 4; c++) acc[i][j][c] = 0.f;

    const int a_row_l = (lane & 15);
    const int a_k_l = (lane >> 4) * 8;
    const int b_row_l = (lane & 7) + (lane >> 4) * 8;
    const int b_k_l = ((lane >> 3) & 1) * 8;

    issue_stage(0, 0);
    int ph[2] = {0, 0};

    for (int kt = 0; kt < NK; kt++) {
        const int st = kt & 1;
        if (kt + 1 < NK) issue_stage(st ^ 1, kt + 1);
        MBARRIER_WAIT_PARITY(mb[st], ph[st]);
        ph[st] ^= 1;

        const uint32_t sb = smem_base + st * G_STAGE_BYTES;
        const uint32_t aHiB = sb + 0 * G_ARR_BYTES;
        const uint32_t aLoB = sb + 1 * G_ARR_BYTES;
        const uint32_t bHiB = sb + 2 * G_ARR_BYTES;
        const uint32_t bLoB = sb + 3 * G_ARR_BYTES;

#pragma unroll
        for (int ks = 0; ks < 4; ks++) {
            const int kk = ks * 16;
            uint32_t ah[4][4], al[4][4], bh[2][4], bl[2][4];
#pragma unroll
            for (int i = 0; i < 4; i++) {
                const int row = wm * 64 + i * 16 + a_row_l;
                const uint32_t off = row * (G_STRIDE * 2) + (kk + a_k_l) * 2;
                ldmat_x4(ah[i], aHiB + off);
                ldmat_x4(al[i], aLoB + off);
            }
#pragma unroll
            for (int j = 0; j < 2; j++) {
                const int nrow = wn * 32 + j * 16 + b_row_l;
                const uint32_t off = nrow * (G_STRIDE * 2) + (kk + b_k_l) * 2;
                ldmat_x4(bh[j], bHiB + off);
                ldmat_x4(bl[j], bLoB + off);
            }
#pragma unroll
            for (int i = 0; i < 4; i++)
#pragma unroll
                for (int j = 0; j < 4; j++) {
                    const uint32_t* bfh = &bh[j >> 1][(j & 1) * 2];
                    const uint32_t* bfl = &bl[j >> 1][(j & 1) * 2];
                    mma_bf16(acc[i][j], ah[i], bfh);
                    mma_bf16(acc[i][j], ah[i], bfl);
                    mma_bf16(acc[i][j], al[i], bfh);
                }
        }
        __syncthreads();   // all reads of stage done before it is re-filled
    }

    // ---- epilogue: bias + store (fp32 OR bf16 hi/lo) ----
    const int qid = lane >> 2;
    const int tq = lane & 3;
#pragma unroll
    for (int j = 0; j < 4; j++) {
        const int col = bn + wn * 32 + j * 8 + tq * 2;
        const float b0 = __ldg(&bias[col]);
        const float b1 = __ldg(&bias[col + 1]);
#pragma unroll
        for (int i = 0; i < 4; i++) {
            const int r0 = bm + wm * 64 + i * 16 + qid;
            const float v0 = acc[i][j][0] + b0, v1 = acc[i][j][1] + b1;
            const float v2 = acc[i][j][2] + b0, v3 = acc[i][j][3] + b1;
            if (Cf) {
                *(float2*)&Cf[(size_t)r0 * Nd + col] = make_float2(v0, v1);
                *(float2*)&Cf[(size_t)(r0 + 8) * Nd + col] = make_float2(v2, v3);
            } else {
                uint32_t h, l;
                split2(v0, v1, h, l);
                *(uint32_t*)&Chi[(size_t)r0 * Nd + col] = h;
                *(uint32_t*)&Clo[(size_t)r0 * Nd + col] = l;
                split2(v2, v3, h, l);
                *(uint32_t*)&Chi[(size_t)(r0 + 8) * Nd + col] = h;
                *(uint32_t*)&Clo[(size_t)(r0 + 8) * Nd + col] = l;
            }
        }
    }
}

// ================= conversion kernels =================
__global__ __launch_bounds__(256) void split_kernel(
    const float* __restrict__ in, __nv_bfloat16* __restrict__ hi,
    __nv_bfloat16* __restrict__ lo, int n4)
{
    int i = blockIdx.x * blockDim.x + threadIdx.x;
    if (i >= n4) return;
    float4 v = ((const float4*)in)[i];
    uint32_t h0, l0, h1, l1;
    split2(v.x, v.y, h0, l0);
    split2(v.z, v.w, h1, l1);
    ((uint32_t*)hi)[i * 2 + 0] = h0;
    ((uint32_t*)hi)[i * 2 + 1] = h1;
    ((uint32_t*)lo)[i * 2 + 0] = l0;
    ((uint32_t*)lo)[i * 2 + 1] = l1;
}

__global__ __launch_bounds__(256) void transpose_split_kernel(
    const float* __restrict__ W, __nv_bfloat16* __restrict__ Th,
    __nv_bfloat16* __restrict__ Tl, int Kd, int Nd)
{
    __shared__ float t[32][33];
    const int k0 = blockIdx.y * 32;
    const int n0 = blockIdx.x * 32;
    const int tx = threadIdx.x;
    const int ty = threadIdx.y;
#pragma unroll
    for (int j = 0; j < 4; j++)
        t[ty + j * 8][tx] = W[(size_t)(k0 + ty + j * 8) * Nd + n0 + tx];
    __syncthreads();
#pragma unroll
    for (int j = 0; j < 4; j++) {
        int n = n0 + ty + j * 8;
        int k = k0 + tx;
        float v = t[tx][ty + j * 8];
        __nv_bfloat16 h = __float2bfloat16_rn(v);
        __nv_bfloat16 l = __float2bfloat16_rn(v - __bfloat162float(h));
        Th[(size_t)n * Kd + k] = h;
        Tl[(size_t)n * Kd + k] = l;
    }
}

// ================= tensor-core flash attention (bulk loader) ==============
#define FL_STRIDE 136                        // padded bf16 per row (272B)
#define FL_Q_BYTES (128 * FL_STRIDE * 2)     // 34816
#define FL_ARR_BYTES (64 * FL_STRIDE * 2)    // 17408
#define FL_STAGE_BYTES (4 * FL_ARR_BYTES)    // 69632
#define FL_KV_OFF (2 * FL_Q_BYTES)
#define FL_MASK_OFF (FL_KV_OFF + 2 * FL_STAGE_BYTES)
#define FL_SMEM (FL_MASK_OFF + SS * 4)       // 217088
#define FL_KV_TX (256 * 256)                 // 64 KB
#define FL_Q_TX (256 * 256 + SS * 4)         // Q + mask

__global__ __launch_bounds__(256, 1)
void flash_tc_kernel(const __nv_bfloat16* __restrict__ Qhi,
                     const __nv_bfloat16* __restrict__ Qlo,
                     const __nv_bfloat16* __restrict__ Khi,
                     const __nv_bfloat16* __restrict__ Klo,
                     const __nv_bfloat16* __restrict__ Vhi,
                     const __nv_bfloat16* __restrict__ Vlo,
                     const float* __restrict__ mask,
                     __nv_bfloat16* __restrict__ Chi,
                     __nv_bfloat16* __restrict__ Clo)
{
    extern __shared__ __align__(128) unsigned char dynsm[];
    __shared__ __align__(16) uint64_t s_mb[3];   // q, kv0, kv1

    const uint32_t sbase = smem_u32(dynsm);
    const uint32_t qhiS = sbase;
    const uint32_t qloS = sbase + FL_Q_BYTES;
    const float* maskS = (const float*)(dynsm + FL_MASK_OFF);

    const int tid = threadIdx.x;
    const int w = tid >> 5;
    const int lane = tid & 31;
    const int b = blockIdx.z;
    const int h = blockIdx.y;
    const int q0 = blockIdx.x * 128;
    const size_t rb = (size_t)b * SS;
    const int hc = h * HDD;

    uint32_t mbq = smem_u32(&s_mb[0]);
    uint32_t mbkv[2];
    mbkv[0] = smem_u32(&s_mb[1]);
    mbkv[1] = smem_u32(&s_mb[2]);

    if (tid == 0) {
        MBARRIER_INIT(mbq, 1);
        MBARRIER_INIT(mbkv[0], 1);
        MBARRIER_INIT(mbkv[1], 1);
    }
    __syncthreads();

    // ---- issue Q (hi/lo) + mask ----
    if (tid == 0) {
        MBARRIER_ARRIVE_EXPECT_TX(mbq, FL_Q_TX);
        bulk_g2s(sbase + FL_MASK_OFF, mask + (size_t)b * SS, SS * 4, mbq);
    }
    {
        const int arr = tid >> 7;            // 0 hi, 1 lo
        const int r = tid & 127;
        const uint32_t dst = (arr ? qloS : qhiS) + r * (FL_STRIDE * 2);
        const __nv_bfloat16* g = (arr ? Qlo : Qhi) + (rb + q0 + r) * HH + hc;
        bulk_g2s(dst, g, 256, mbq);
    }

    auto issue_kv = [&](int st, int kt) {
        if (tid == 0) MBARRIER_ARRIVE_EXPECT_TX(mbkv[st], FL_KV_TX);
        const int k0 = kt * 64;
        const uint32_t sb = sbase + FL_KV_OFF + st * FL_STAGE_BYTES;
        const int arr = tid >> 6;            // 0 Khi,1 Klo,2 Vhi,3 Vlo
        const int r = tid & 63;
        const uint32_t dst = sb + arr * FL_ARR_BYTES + r * (FL_STRIDE * 2);
        const __nv_bfloat16* g;
        const size_t go = (rb + k0 + r) * HH + hc;
        if (arr == 0)      g = Khi + go;
        else if (arr == 1) g = Klo + go;
        else if (arr == 2) g = Vhi + go;
        else               g = Vlo + go;
        bulk_g2s(dst, g, 256, mbkv[st]);
    };

    issue_kv(0, 0);

    const float sc2 = 0.08838834764831845f * 1.4426950408889634f;
    const float L2E = 1.4426950408889634f;

    float o[16][4];
#pragma unroll
    for (int t = 0; t < 16; t++)
#pragma unroll
        for (int c = 0; c < 4; c++) o[t][c] = 0.f;
    float m0 = -1e30f, m1 = -1e30f, l0 = 0.f, l1 = 0.f;

    const int a_row_l = (lane & 15);
    const int a_k_l = (lane >> 4) * 8;
    const int b_row_l = (lane & 7) + (lane >> 4) * 8;
    const int b_k_l = ((lane >> 3) & 1) * 8;
    const int v_row_l = (lane & 7) + ((lane >> 3) & 1) * 8;
    const int v_col_l = (lane >> 4) * 8;
    const int tq2 = (lane & 3) * 2;

    MBARRIER_WAIT_PARITY(mbq, 0);   // Q + mask resident
    int ph[2] = {0, 0};

    for (int kt = 0; kt < SS / 64; kt++) {
        const int st = kt & 1;
        if (kt + 1 < SS / 64) issue_kv(st ^ 1, kt + 1);
        MBARRIER_WAIT_PARITY(mbkv[st], ph[st]);
        ph[st] ^= 1;

        const uint32_t sb = sbase + FL_KV_OFF + st * FL_STAGE_BYTES;
        const uint32_t kHiB = sb + 0 * FL_ARR_BYTES;
        const uint32_t kLoB = sb + 1 * FL_ARR_BYTES;
        const uint32_t vHiB = sb + 2 * FL_ARR_BYTES;
        const uint32_t vLoB = sb + 3 * FL_ARR_BYTES;

        // ---- S = Q K^T ----
        float s[8][4];
#pragma unroll
        for (int j = 0; j < 8; j++)
#pragma unroll
            for (int c = 0; c < 4; c++) s[j][c] = 0.f;

#pragma unroll
        for (int ks = 0; ks < 8; ks++) {
            uint32_t qh[4], ql[4];
            const uint32_t qoff = (w * 16 + a_row_l) * (FL_STRIDE * 2) +
                                  (ks * 16 + a_k_l) * 2;
            ldmat_x4(qh, qhiS + qoff);
            ldmat_x4(ql, qloS + qoff);
#pragma unroll
            for (int j = 0; j < 4; j++) {
                uint32_t kh[4], kl[4];
                const uint32_t koff = (j * 16 + b_row_l) * (FL_STRIDE * 2) +
                                      (ks * 16 + b_k_l) * 2;
                ldmat_x4(kh, kHiB + koff);
                ldmat_x4(kl, kLoB + koff);
                mma_bf16(s[2 * j], qh, &kh[0]);
                mma_bf16(s[2 * j], qh, &kl[0]);
                mma_bf16(s[2 * j], ql, &kh[0]);
                mma_bf16(s[2 * j + 1], qh, &kh[2]);
                mma_bf16(s[2 * j + 1], qh, &kl[2]);
                mma_bf16(s[2 * j + 1], ql, &kh[2]);
            }
        }

        // ---- scale + mask (exp2 domain) ----
#pragma unroll
        for (int j = 0; j < 8; j++) {
            const float mk0 = maskS[kt * 64 + j * 8 + tq2] * L2E;
            const float mk1 = maskS[kt * 64 + j * 8 + tq2 + 1] * L2E;
            s[j][0] = fmaf(s[j][0], sc2, mk0);
            s[j][1] = fmaf(s[j][1], sc2, mk1);
            s[j][2] = fmaf(s[j][2], sc2, mk0);
            s[j][3] = fmaf(s[j][3], sc2, mk1);
        }

        // ---- online softmax ----
        float rm0 = -1e30f, rm1 = -1e30f;
#pragma unroll
        for (int j = 0; j < 8; j++) {
            rm0 = fmaxf(rm0, fmaxf(s[j][0], s[j][1]));
            rm1 = fmaxf(rm1, fmaxf(s[j][2], s[j][3]));
        }
        rm0 = fmaxf(rm0, __shfl_xor_sync(0xffffffffu, rm0, 1));
        rm0 = fmaxf(rm0, __shfl_xor_sync(0xffffffffu, rm0, 2));
        rm1 = fmaxf(rm1, __shfl_xor_sync(0xffffffffu, rm1, 1));
        rm1 = fmaxf(rm1, __shfl_xor_sync(0xffffffffu, rm1, 2));
        const float nm0 = fmaxf(m0, rm0), nm1 = fmaxf(m1, rm1);
        const float corr0 = exp2f(m0 - nm0), corr1 = exp2f(m1 - nm1);
        float sum0 = 0.f, sum1 = 0.f;
#pragma unroll
        for (int j = 0; j < 8; j++) {
            s[j][0] = exp2f(s[j][0] - nm0);
            s[j][1] = exp2f(s[j][1] - nm0);
            s[j][2] = exp2f(s[j][2] - nm1);
            s[j][3] = exp2f(s[j][3] - nm1);
            sum0 += s[j][0] + s[j][1];
            sum1 += s[j][2] + s[j][3];
        }
        sum0 += __shfl_xor_sync(0xffffffffu, sum0, 1);
        sum0 += __shfl_xor_sync(0xffffffffu, sum0, 2);
        sum1 += __shfl_xor_sync(0xffffffffu, sum1, 1);
        sum1 += __shfl_xor_sync(0xffffffffu, sum1, 2);
        l0 = l0 * corr0 + sum0;
        l1 = l1 * corr1 + sum1;
        m0 = nm0; m1 = nm1;
#pragma unroll
        for (int t = 0; t < 16; t++) {
            o[t][0] *= corr0; o[t][1] *= corr0;
            o[t][2] *= corr1; o[t][3] *= corr1;
        }

        // ---- O += P V ----
#pragma unroll
        for (int ks = 0; ks < 4; ks++) {
            uint32_t ahi[4], alo[4];
            split2(s[2 * ks][0], s[2 * ks][1], ahi[0], alo[0]);
            split2(s[2 * ks][2], s[2 * ks][3], ahi[1], alo[1]);
            split2(s[2 * ks + 1][0], s[2 * ks + 1][1], ahi[2], alo[2]);
            split2(s[2 * ks + 1][2], s[2 * ks + 1][3], ahi[3], alo[3]);
#pragma unroll
            for (int j = 0; j < 8; j++) {
                uint32_t vh[4], vl[4];
                const uint32_t voff = (ks * 16 + v_row_l) * (FL_STRIDE * 2) +
                                      (j * 16 + v_col_l) * 2;
                ldmat_x4_t(vh, vHiB + voff);
                ldmat_x4_t(vl, vLoB + voff);
                mma_bf16(o[2 * j], ahi, &vh[0]);
                mma_bf16(o[2 * j], ahi, &vl[0]);
                mma_bf16(o[2 * j], alo, &vh[0]);
                mma_bf16(o[2 * j + 1], ahi, &vh[2]);
                mma_bf16(o[2 * j + 1], ahi, &vl[2]);
                mma_bf16(o[2 * j + 1], alo, &vh[2]);
            }
        }
        __syncthreads();   // stage reads done before re-fill
    }

    // ---- normalize + write ctx (bf16 hi/lo) ----
    const float inv0 = 1.f / l0, inv1 = 1.f / l1;
    const int g = lane >> 2;
    const size_t row0 = rb + q0 + w * 16 + g;
    const size_t row1 = row0 + 8;
#pragma unroll
    for (int t = 0; t < 16; t++) {
        const int col = hc + t * 8 + tq2;
        uint32_t hi, lo;
        split2(o[t][0] * inv0, o[t][1] * inv0, hi, lo);
        *(uint32_t*)&Chi[row0 * HH + col] = hi;
        *(uint32_t*)&Clo[row0 * HH + col] = lo;
        split2(o[t][2] * inv1, o[t][3] * inv1, hi, lo);
        *(uint32_t*)&Chi[row1 * HH + col] = hi;
        *(uint32_t*)&Clo[row1 * HH + col] = lo;
    }
}

// ---------------- launch ----------------
extern "C" void kernel_launch(void* const* d_in, const int* in_sizes, int n_in,
                              void* d_out, int out_size)
{
    (void)in_sizes; (void)n_in; (void)out_size;
    const float* x    = (const float*)d_in[0];
    const float* mask = (const float*)d_in[1];
    const float* Wq   = (const float*)d_in[2];
    const float* bq   = (const float*)d_in[3];
    const float* Wk   = (const float*)d_in[4];
    const float* bk   = (const float*)d_in[5];
    const float* Wv   = (const float*)d_in[6];
    const float* bv   = (const float*)d_in[7];
    const float* Wo   = (const float*)d_in[8];
    const float* bo   = (const float*)d_in[9];
    float* out = (float*)d_out;

    __nv_bfloat16 *qhi, *qlo, *khi, *klo, *vhi, *vlo, *xhi, *xlo, *wthi, *wtlo;
    cudaGetSymbolAddress((void**)&qhi, g_Qhi);
    cudaGetSymbolAddress((void**)&qlo, g_Qlo);
    cudaGetSymbolAddress((void**)&khi, g_Khi);
    cudaGetSymbolAddress((void**)&klo, g_Klo);
    cudaGetSymbolAddress((void**)&vhi, g_Vhi);
    cudaGetSymbolAddress((void**)&vlo, g_Vlo);
    cudaGetSymbolAddress((void**)&xhi, g_xhi);
    cudaGetSymbolAddress((void**)&xlo, g_xlo);
    cudaGetSymbolAddress((void**)&wthi, g_wthi);
    cudaGetSymbolAddress((void**)&wtlo, g_wtlo);

    cudaFuncSetAttribute(gemm_tc_kernel,
                         cudaFuncAttributeMaxDynamicSharedMemorySize, G_SMEM_BYTES);
    cudaFuncSetAttribute(flash_tc_kernel,
                         cudaFuncAttributeMaxDynamicSharedMemorySize, FL_SMEM);

    const int n4 = (MROWS * HH) / 4;
    dim3 tgrid(HH / 32, HH / 32);
    dim3 tblk(32, 8);
    dim3 ggrid(HH / G_BN, MROWS / G_BM);

    // split x once
    split_kernel<<<(n4 + 255) / 256, 256>>>(x, xhi, xlo, n4);

    // Q, K, V projections -> bf16 hi/lo directly
    transpose_split_kernel<<<tgrid, tblk>>>(Wq, wthi, wtlo, HH, HH);
    gemm_tc_kernel<<<ggrid, 256, G_SMEM_BYTES>>>(xhi, xlo, wthi, wtlo, bq,
                                                 nullptr, qhi, qlo, HH, HH);
    transpose_split_kernel<<<tgrid, tblk>>>(Wk, wthi, wtlo, HH, HH);
    gemm_tc_kernel<<<ggrid, 256, G_SMEM_BYTES>>>(xhi, xlo, wthi, wtlo, bk,
                                                 nullptr, khi, klo, HH, HH);
    transpose_split_kernel<<<tgrid, tblk>>>(Wv, wthi, wtlo, HH, HH);
    gemm_tc_kernel<<<ggrid, 256, G_SMEM_BYTES>>>(xhi, xlo, wthi, wtlo, bv,
                                                 nullptr, vhi, vlo, HH, HH);

    // attention (writes ctx hi/lo into xhi/xlo, which are free now)
    flash_tc_kernel<<<dim3(SS / 128, NHH, BB), 256, FL_SMEM>>>(
        qhi, qlo, khi, klo, vhi, vlo, mask, xhi, xlo);

    // output projection -> fp32 out
    transpose_split_kernel<<<tgrid, tblk>>>(Wo, wthi, wtlo, HH, HH);
    gemm_tc_kernel<<<ggrid, 256, G_SMEM_BYTES>>>(xhi, xlo, wthi, wtlo, bo,
                                                 out, nullptr, nullptr, HH, HH);
}

// round 6
// speedup vs baseline: 1.9482x; 1.9482x over previous
#include <cuda_runtime.h>
#include <cuda_fp16.h>
#include <math.h>
#include <stdint.h>

// Problem constants
#define BB 2
#define SS 2048
#define HH 2048
#define NHH 16
#define HDD 128
#define MROWS (BB * SS)   // 4096

// ---------------- scratch (no allocations allowed) ----------------
__device__ __half g_Qhi[(size_t)MROWS * HH];
__device__ __half g_Qlo[(size_t)MROWS * HH];
__device__ __half g_Khi[(size_t)MROWS * HH];
__device__ __half g_Vhi[(size_t)MROWS * HH];
__device__ __half g_xhi[(size_t)MROWS * HH];
__device__ __half g_xlo[(size_t)MROWS * HH];
__device__ __half g_wt[(size_t)HH * HH];

// ================= PTX helpers (baseline ISA only) ===========
__device__ __forceinline__ uint32_t smem_u32(const void* p) {
    uint32_t a;
    asm("{ .reg .u64 t; cvta.to.shared.u64 t, %1; cvt.u32.u64 %0, t; }"
        : "=r"(a) : "l"(p));
    return a;
}

__device__ __forceinline__ void cp_async16(uint32_t smem, const void* g) {
    asm volatile("cp.async.cg.shared.global [%0], [%1], 16;"
                 :: "r"(smem), "l"(g) : "memory");
}
#define CP_COMMIT() asm volatile("cp.async.commit_group;" ::: "memory")
template <int N>
__device__ __forceinline__ void cp_wait() {
    asm volatile("cp.async.wait_group %0;" :: "n"(N) : "memory");
}

__device__ __forceinline__ void ldmat_x4(uint32_t* r, uint32_t addr) {
    asm volatile("ldmatrix.sync.aligned.m8n8.x4.shared.b16 {%0,%1,%2,%3}, [%4];"
                 : "=r"(r[0]), "=r"(r[1]), "=r"(r[2]), "=r"(r[3]) : "r"(addr));
}
__device__ __forceinline__ void ldmat_x4_t(uint32_t* r, uint32_t addr) {
    asm volatile("ldmatrix.sync.aligned.m8n8.x4.trans.shared.b16 {%0,%1,%2,%3}, [%4];"
                 : "=r"(r[0]), "=r"(r[1]), "=r"(r[2]), "=r"(r[3]) : "r"(addr));
}

__device__ __forceinline__ void mma_f16(float* d, const uint32_t* a, const uint32_t* b) {
    asm volatile(
        "mma.sync.aligned.m16n8k16.row.col.f32.f16.f16.f32 "
        "{%0,%1,%2,%3}, {%4,%5,%6,%7}, {%8,%9}, {%0,%1,%2,%3};"
        : "+f"(d[0]), "+f"(d[1]), "+f"(d[2]), "+f"(d[3])
        : "r"(a[0]), "r"(a[1]), "r"(a[2]), "r"(a[3]), "r"(b[0]), "r"(b[1]));
}

// split two floats into fp16 hi pair + lo pair (packed u32)
__device__ __forceinline__ void split2h(float a, float b, uint32_t& hi, uint32_t& lo) {
    __half ha = __float2half_rn(a);
    __half hb = __float2half_rn(b);
    __half2 h2 = __halves2half2(ha, hb);
    hi = *(uint32_t*)&h2;
    __half2 l2 = __floats2half2_rn(a - __half2float(ha), b - __half2float(hb));
    lo = *(uint32_t*)&l2;
}

__device__ __forceinline__ uint32_t pack2h(float a, float b) {
    __half2 h2 = __floats2half2_rn(a, b);
    return *(uint32_t*)&h2;
}

// ================= fp16 split-A GEMM via mma.sync =================
// C[M,N] = (Ahi+Alo)[M,K] @ B[N,K]^T + bias.  B single fp16.
// Tile 128x128x64, 2 cp.async stages, 256 threads (2x4 warps, warp 64x32).
#define G_BM 128
#define G_BN 128
#define G_BK 64
#define G_STRIDE 72                           // fp16 elems per row (64+8 pad)
#define G_ARR_BYTES (128 * G_STRIDE * 2)      // 18432
#define G_STAGE_BYTES (3 * G_ARR_BYTES)       // 55296
#define G_SMEM_BYTES (2 * G_STAGE_BYTES)      // 110592

__global__ __launch_bounds__(256, 1)
void gemm_tc_kernel(const __half* __restrict__ Ahi,
                    const __half* __restrict__ Alo,
                    const __half* __restrict__ B,
                    const float* __restrict__ bias,
                    float* __restrict__ Cf,
                    __half* __restrict__ Chi,
                    __half* __restrict__ Clo,
                    int Kd, int Nd)
{
    extern __shared__ __align__(128) unsigned char dynsm[];
    const int tid = threadIdx.x;
    const int wid = tid >> 5;
    const int lane = tid & 31;
    const int wm = wid & 1;
    const int wn = wid >> 1;
    const int bm = blockIdx.y * G_BM;
    const int bn = blockIdx.x * G_BN;
    const int NK = Kd / G_BK;   // 32

    const uint32_t smem_base = smem_u32(dynsm);

    // loader: 3 arrays x 128 rows x 8 chunks of 16B = 3072 ops, 12/thread
    auto load_stage = [&](int st, int kt) {
        const int k0 = kt * G_BK;
        const uint32_t sb = smem_base + st * G_STAGE_BYTES;
#pragma unroll
        for (int i = tid; i < 3072; i += 256) {
            const int arr = i >> 10;
            const int t = i & 1023;
            const int r = t >> 3;
            const int c = t & 7;
            const uint32_t soff = sb + arr * G_ARR_BYTES + r * (G_STRIDE * 2) + c * 16;
            const __half* g;
            if (arr == 0)      g = Ahi + (size_t)(bm + r) * Kd + k0 + c * 8;
            else if (arr == 1) g = Alo + (size_t)(bm + r) * Kd + k0 + c * 8;
            else               g = B + (size_t)(bn + r) * Kd + k0 + c * 8;
            cp_async16(soff, g);
        }
        CP_COMMIT();
    };

    float acc[4][4][4];
#pragma unroll
    for (int i = 0; i < 4; i++)
#pragma unroll
        for (int j = 0; j < 4; j++)
#pragma unroll
            for (int c = 0; c < 4; c++) acc[i][j][c] = 0.f;

    const int a_row_l = (lane & 15);
    const int a_k_l = (lane >> 4) * 8;
    const int b_row_l = (lane & 7) + (lane >> 4) * 8;
    const int b_k_l = ((lane >> 3) & 1) * 8;

    load_stage(0, 0);

    for (int kt = 0; kt < NK; kt++) {
        if (kt + 1 < NK) load_stage((kt + 1) & 1, kt + 1);
        else CP_COMMIT();
        cp_wait<1>();
        __syncthreads();

        const uint32_t sb = smem_base + (kt & 1) * G_STAGE_BYTES;
        const uint32_t aHiB = sb + 0 * G_ARR_BYTES;
        const uint32_t aLoB = sb + 1 * G_ARR_BYTES;
        const uint32_t bB   = sb + 2 * G_ARR_BYTES;

#pragma unroll
        for (int ks = 0; ks < 4; ks++) {
            const int kk = ks * 16;
            uint32_t ah[4][4], al[4][4], bh[2][4];
#pragma unroll
            for (int i = 0; i < 4; i++) {
                const int row = wm * 64 + i * 16 + a_row_l;
                const uint32_t off = row * (G_STRIDE * 2) + (kk + a_k_l) * 2;
                ldmat_x4(ah[i], aHiB + off);
                ldmat_x4(al[i], aLoB + off);
            }
#pragma unroll
            for (int j = 0; j < 2; j++) {
                const int nrow = wn * 32 + j * 16 + b_row_l;
                const uint32_t off = nrow * (G_STRIDE * 2) + (kk + b_k_l) * 2;
                ldmat_x4(bh[j], bB + off);
            }
#pragma unroll
            for (int i = 0; i < 4; i++)
#pragma unroll
                for (int j = 0; j < 4; j++) {
                    const uint32_t* bf = &bh[j >> 1][(j & 1) * 2];
                    mma_f16(acc[i][j], ah[i], bf);
                    mma_f16(acc[i][j], al[i], bf);
                }
        }
        __syncthreads();
    }

    // ---- epilogue: bias + store (fp32 | fp16 split | fp16 single) ----
    const int qid = lane >> 2;
    const int tq = lane & 3;
#pragma unroll
    for (int j = 0; j < 4; j++) {
        const int col = bn + wn * 32 + j * 8 + tq * 2;
        const float b0 = __ldg(&bias[col]);
        const float b1 = __ldg(&bias[col + 1]);
#pragma unroll
        for (int i = 0; i < 4; i++) {
            const int r0 = bm + wm * 64 + i * 16 + qid;
            const float v0 = acc[i][j][0] + b0, v1 = acc[i][j][1] + b1;
            const float v2 = acc[i][j][2] + b0, v3 = acc[i][j][3] + b1;
            if (Cf) {
                *(float2*)&Cf[(size_t)r0 * Nd + col] = make_float2(v0, v1);
                *(float2*)&Cf[(size_t)(r0 + 8) * Nd + col] = make_float2(v2, v3);
            } else if (Clo) {
                uint32_t h, l;
                split2h(v0, v1, h, l);
                *(uint32_t*)&Chi[(size_t)r0 * Nd + col] = h;
                *(uint32_t*)&Clo[(size_t)r0 * Nd + col] = l;
                split2h(v2, v3, h, l);
                *(uint32_t*)&Chi[(size_t)(r0 + 8) * Nd + col] = h;
                *(uint32_t*)&Clo[(size_t)(r0 + 8) * Nd + col] = l;
            } else {
                *(uint32_t*)&Chi[(size_t)r0 * Nd + col] = pack2h(v0, v1);
                *(uint32_t*)&Chi[(size_t)(r0 + 8) * Nd + col] = pack2h(v2, v3);
            }
        }
    }
}

// ================= conversion kernels =================
__global__ __launch_bounds__(256) void split_kernel(
    const float* __restrict__ in, __half* __restrict__ hi,
    __half* __restrict__ lo, int n4)
{
    int i = blockIdx.x * blockDim.x + threadIdx.x;
    if (i >= n4) return;
    float4 v = ((const float4*)in)[i];
    uint32_t h0, l0, h1, l1;
    split2h(v.x, v.y, h0, l0);
    split2h(v.z, v.w, h1, l1);
    ((uint32_t*)hi)[i * 2 + 0] = h0;
    ((uint32_t*)hi)[i * 2 + 1] = h1;
    ((uint32_t*)lo)[i * 2 + 0] = l0;
    ((uint32_t*)lo)[i * 2 + 1] = l1;
}

// W[K][N] fp32 -> Wt[N][K] fp16 single
__global__ __launch_bounds__(256) void transpose_h_kernel(
    const float* __restrict__ W, __half* __restrict__ Th, int Kd, int Nd)
{
    __shared__ float t[32][33];
    const int k0 = blockIdx.y * 32;
    const int n0 = blockIdx.x * 32;
    const int tx = threadIdx.x;
    const int ty = threadIdx.y;
#pragma unroll
    for (int j = 0; j < 4; j++)
        t[ty + j * 8][tx] = W[(size_t)(k0 + ty + j * 8) * Nd + n0 + tx];
    __syncthreads();
#pragma unroll
    for (int j = 0; j < 4; j++) {
        int n = n0 + ty + j * 8;
        int k = k0 + tx;
        Th[(size_t)n * Kd + k] = __float2half_rn(t[tx][ty + j * 8]);
    }
}

// ================= tensor-core flash attention (fp16) =================
// CTA: 128 q-rows x one head. Q split (hi/lo), K/V single fp16.
#define FL_STRIDE 136                        // padded fp16 per row (272B)
#define FL_Q_BYTES (128 * FL_STRIDE * 2)     // 34816
#define FL_ARR_BYTES (64 * FL_STRIDE * 2)    // 17408
#define FL_STAGE_BYTES (2 * FL_ARR_BYTES)    // 34816 (K, V)
#define FL_KV_OFF (2 * FL_Q_BYTES)
#define FL_MASK_OFF (FL_KV_OFF + 2 * FL_STAGE_BYTES)
#define FL_SMEM (FL_MASK_OFF + SS * 4)       // 147456

__global__ __launch_bounds__(256, 1)
void flash_tc_kernel(const __half* __restrict__ Qhi,
                     const __half* __restrict__ Qlo,
                     const __half* __restrict__ Kh,
                     const __half* __restrict__ Vh,
                     const float* __restrict__ mask,
                     __half* __restrict__ Chi,
                     __half* __restrict__ Clo)
{
    extern __shared__ __align__(128) unsigned char dynsm[];
    const uint32_t sbase = smem_u32(dynsm);
    const uint32_t qhiS = sbase;
    const uint32_t qloS = sbase + FL_Q_BYTES;
    const float* maskS = (const float*)(dynsm + FL_MASK_OFF);

    const int tid = threadIdx.x;
    const int w = tid >> 5;
    const int lane = tid & 31;
    const int b = blockIdx.z;
    const int h = blockIdx.y;
    const int q0 = blockIdx.x * 128;
    const size_t rb = (size_t)b * SS;
    const int hc = h * HDD;

    // ---- load Q (hi/lo) + mask ----
#pragma unroll
    for (int i = tid; i < 4096; i += 256) {
        const int arr = i >> 11;
        const int t = i & 2047;
        const int r = t >> 4;
        const int c = t & 15;
        const uint32_t soff = (arr ? qloS : qhiS) + r * (FL_STRIDE * 2) + c * 16;
        const __half* g = (arr ? Qlo : Qhi) + (rb + q0 + r) * HH + hc + c * 8;
        cp_async16(soff, g);
    }
#pragma unroll
    for (int i = tid; i < 512; i += 256)
        cp_async16(sbase + FL_MASK_OFF + i * 16, mask + (size_t)b * SS + i * 4);

    auto load_kv = [&](int st, int kt) {
        const int k0 = kt * 64;
        const uint32_t sb = sbase + FL_KV_OFF + st * FL_STAGE_BYTES;
#pragma unroll
        for (int i = tid; i < 2048; i += 256) {
            const int arr = i >> 10;          // 0 K, 1 V
            const int t = i & 1023;
            const int r = t >> 4;
            const int c = t & 15;
            const uint32_t soff = sb + arr * FL_ARR_BYTES + r * (FL_STRIDE * 2) + c * 16;
            const size_t go = (rb + k0 + r) * HH + hc + c * 8;
            cp_async16(soff, (arr ? Vh : Kh) + go);
        }
        CP_COMMIT();
    };

    load_kv(0, 0);   // group 0 also contains Q + mask

    const float sc2 = 0.08838834764831845f * 1.4426950408889634f; // scale*log2e
    const float L2E = 1.4426950408889634f;

    float o[16][4];
#pragma unroll
    for (int t = 0; t < 16; t++)
#pragma unroll
        for (int c = 0; c < 4; c++) o[t][c] = 0.f;
    float m0 = -1e30f, m1 = -1e30f, l0 = 0.f, l1 = 0.f;

    const int a_row_l = (lane & 15);
    const int a_k_l = (lane >> 4) * 8;
    const int b_row_l = (lane & 7) + (lane >> 4) * 8;
    const int b_k_l = ((lane >> 3) & 1) * 8;
    const int v_row_l = (lane & 7) + ((lane >> 3) & 1) * 8;
    const int v_col_l = (lane >> 4) * 8;
    const int tq2 = (lane & 3) * 2;

    __syncthreads();

    for (int kt = 0; kt < SS / 64; kt++) {
        if (kt + 1 < SS / 64) load_kv((kt + 1) & 1, kt + 1);
        else CP_COMMIT();
        cp_wait<1>();
        __syncthreads();

        const uint32_t sb = sbase + FL_KV_OFF + (kt & 1) * FL_STAGE_BYTES;
        const uint32_t kB = sb + 0 * FL_ARR_BYTES;
        const uint32_t vB = sb + 1 * FL_ARR_BYTES;

        // ---- S = Q K^T ----
        float s[8][4];
#pragma unroll
        for (int j = 0; j < 8; j++)
#pragma unroll
            for (int c = 0; c < 4; c++) s[j][c] = 0.f;

#pragma unroll
        for (int ks = 0; ks < 8; ks++) {
            uint32_t qh[4], ql[4];
            const uint32_t qoff = (w * 16 + a_row_l) * (FL_STRIDE * 2) +
                                  (ks * 16 + a_k_l) * 2;
            ldmat_x4(qh, qhiS + qoff);
            ldmat_x4(ql, qloS + qoff);
#pragma unroll
            for (int j = 0; j < 4; j++) {
                uint32_t kh[4];
                const uint32_t koff = (j * 16 + b_row_l) * (FL_STRIDE * 2) +
                                      (ks * 16 + b_k_l) * 2;
                ldmat_x4(kh, kB + koff);
                mma_f16(s[2 * j], qh, &kh[0]);
                mma_f16(s[2 * j], ql, &kh[0]);
                mma_f16(s[2 * j + 1], qh, &kh[2]);
                mma_f16(s[2 * j + 1], ql, &kh[2]);
            }
        }

        // ---- scale + mask (exp2 domain) ----
#pragma unroll
        for (int j = 0; j < 8; j++) {
            const float mk0 = maskS[kt * 64 + j * 8 + tq2] * L2E;
            const float mk1 = maskS[kt * 64 + j * 8 + tq2 + 1] * L2E;
            s[j][0] = fmaf(s[j][0], sc2, mk0);
            s[j][1] = fmaf(s[j][1], sc2, mk1);
            s[j][2] = fmaf(s[j][2], sc2, mk0);
            s[j][3] = fmaf(s[j][3], sc2, mk1);
        }

        // ---- online softmax ----
        float rm0 = -1e30f, rm1 = -1e30f;
#pragma unroll
        for (int j = 0; j < 8; j++) {
            rm0 = fmaxf(rm0, fmaxf(s[j][0], s[j][1]));
            rm1 = fmaxf(rm1, fmaxf(s[j][2], s[j][3]));
        }
        rm0 = fmaxf(rm0, __shfl_xor_sync(0xffffffffu, rm0, 1));
        rm0 = fmaxf(rm0, __shfl_xor_sync(0xffffffffu, rm0, 2));
        rm1 = fmaxf(rm1, __shfl_xor_sync(0xffffffffu, rm1, 1));
        rm1 = fmaxf(rm1, __shfl_xor_sync(0xffffffffu, rm1, 2));
        const float nm0 = fmaxf(m0, rm0), nm1 = fmaxf(m1, rm1);
        const float corr0 = exp2f(m0 - nm0), corr1 = exp2f(m1 - nm1);
        float sum0 = 0.f, sum1 = 0.f;
#pragma unroll
        for (int j = 0; j < 8; j++) {
            s[j][0] = exp2f(s[j][0] - nm0);
            s[j][1] = exp2f(s[j][1] - nm0);
            s[j][2] = exp2f(s[j][2] - nm1);
            s[j][3] = exp2f(s[j][3] - nm1);
            sum0 += s[j][0] + s[j][1];
            sum1 += s[j][2] + s[j][3];
        }
        sum0 += __shfl_xor_sync(0xffffffffu, sum0, 1);
        sum0 += __shfl_xor_sync(0xffffffffu, sum0, 2);
        sum1 += __shfl_xor_sync(0xffffffffu, sum1, 1);
        sum1 += __shfl_xor_sync(0xffffffffu, sum1, 2);
        l0 = l0 * corr0 + sum0;
        l1 = l1 * corr1 + sum1;
        m0 = nm0; m1 = nm1;
#pragma unroll
        for (int t = 0; t < 16; t++) {
            o[t][0] *= corr0; o[t][1] *= corr0;
            o[t][2] *= corr1; o[t][3] *= corr1;
        }

        // ---- O += P V  (P split fp16, V single) ----
#pragma unroll
        for (int ks = 0; ks < 4; ks++) {
            uint32_t ph[4], pl[4];
            split2h(s[2 * ks][0], s[2 * ks][1], ph[0], pl[0]);
            split2h(s[2 * ks][2], s[2 * ks][3], ph[1], pl[1]);
            split2h(s[2 * ks + 1][0], s[2 * ks + 1][1], ph[2], pl[2]);
            split2h(s[2 * ks + 1][2], s[2 * ks + 1][3], ph[3], pl[3]);
#pragma unroll
            for (int j = 0; j < 8; j++) {
                uint32_t vh[4];
                const uint32_t voff = (ks * 16 + v_row_l) * (FL_STRIDE * 2) +
                                      (j * 16 + v_col_l) * 2;
                ldmat_x4_t(vh, vB + voff);
                mma_f16(o[2 * j], ph, &vh[0]);
                mma_f16(o[2 * j], pl, &vh[0]);
                mma_f16(o[2 * j + 1], ph, &vh[2]);
                mma_f16(o[2 * j + 1], pl, &vh[2]);
            }
        }
        __syncthreads();
    }

    // ---- normalize + write ctx (fp16 hi/lo) ----
    const float inv0 = 1.f / l0, inv1 = 1.f / l1;
    const int g = lane >> 2;
    const size_t row0 = rb + q0 + w * 16 + g;
    const size_t row1 = row0 + 8;
#pragma unroll
    for (int t = 0; t < 16; t++) {
        const int col = hc + t * 8 + tq2;
        uint32_t hi, lo;
        split2h(o[t][0] * inv0, o[t][1] * inv0, hi, lo);
        *(uint32_t*)&Chi[row0 * HH + col] = hi;
        *(uint32_t*)&Clo[row0 * HH + col] = lo;
        split2h(o[t][2] * inv1, o[t][3] * inv1, hi, lo);
        *(uint32_t*)&Chi[row1 * HH + col] = hi;
        *(uint32_t*)&Clo[row1 * HH + col] = lo;
    }
}

// ---------------- launch ----------------
extern "C" void kernel_launch(void* const* d_in, const int* in_sizes, int n_in,
                              void* d_out, int out_size)
{
    (void)in_sizes; (void)n_in; (void)out_size;
    const float* x    = (const float*)d_in[0];
    const float* mask = (const float*)d_in[1];
    const float* Wq   = (const float*)d_in[2];
    const float* bq   = (const float*)d_in[3];
    const float* Wk   = (const float*)d_in[4];
    const float* bk   = (const float*)d_in[5];
    const float* Wv   = (const float*)d_in[6];
    const float* bv   = (const float*)d_in[7];
    const float* Wo   = (const float*)d_in[8];
    const float* bo   = (const float*)d_in[9];
    float* out = (float*)d_out;

    __half *qhi, *qlo, *khi, *vhi, *xhi, *xlo, *wt;
    cudaGetSymbolAddress((void**)&qhi, g_Qhi);
    cudaGetSymbolAddress((void**)&qlo, g_Qlo);
    cudaGetSymbolAddress((void**)&khi, g_Khi);
    cudaGetSymbolAddress((void**)&vhi, g_Vhi);
    cudaGetSymbolAddress((void**)&xhi, g_xhi);
    cudaGetSymbolAddress((void**)&xlo, g_xlo);
    cudaGetSymbolAddress((void**)&wt, g_wt);

    cudaFuncSetAttribute(gemm_tc_kernel,
                         cudaFuncAttributeMaxDynamicSharedMemorySize, G_SMEM_BYTES);
    cudaFuncSetAttribute(flash_tc_kernel,
                         cudaFuncAttributeMaxDynamicSharedMemorySize, FL_SMEM);

    const int n4 = (MROWS * HH) / 4;
    dim3 tgrid(HH / 32, HH / 32);
    dim3 tblk(32, 8);
    dim3 ggrid(HH / G_BN, MROWS / G_BM);

    // split x once (A operand of QKV projections)
    split_kernel<<<(n4 + 255) / 256, 256>>>(x, xhi, xlo, n4);

    // Q projection -> split fp16; K, V projections -> single fp16
    transpose_h_kernel<<<tgrid, tblk>>>(Wq, wt, HH, HH);
    gemm_tc_kernel<<<ggrid, 256, G_SMEM_BYTES>>>(xhi, xlo, wt, bq,
                                                 nullptr, qhi, qlo, HH, HH);
    transpose_h_kernel<<<tgrid, tblk>>>(Wk, wt, HH, HH);
    gemm_tc_kernel<<<ggrid, 256, G_SMEM_BYTES>>>(xhi, xlo, wt, bk,
                                                 nullptr, khi, nullptr, HH, HH);
    transpose_h_kernel<<<tgrid, tblk>>>(Wv, wt, HH, HH);
    gemm_tc_kernel<<<ggrid, 256, G_SMEM_BYTES>>>(xhi, xlo, wt, bv,
                                                 nullptr, vhi, nullptr, HH, HH);

    // attention (writes ctx hi/lo into xhi/xlo, which are free now)
    flash_tc_kernel<<<dim3(SS / 128, NHH, BB), 256, FL_SMEM>>>(
        qhi, qlo, khi, vhi, mask, xhi, xlo);

    // output projection -> fp32 out
    transpose_h_kernel<<<tgrid, tblk>>>(Wo, wt, HH, HH);
    gemm_tc_kernel<<<ggrid, 256, G_SMEM_BYTES>>>(xhi, xlo, wt, bo,
                                                 out, nullptr, nullptr, HH, HH);
}